// round 12
// baseline (speedup 1.0000x reference)
#include <cuda_runtime.h>
#include <cuda_bf16.h>
#include <math.h>
#include <stdint.h>

#define NN 50000
#define EE 800000
#define BG 512
#define D  128
#define SCAN_BLKS 49   // ceil(50000 / 1024)

// ---------------- scratch (static device globals; no allocation) ----------------
__device__ int   g_deg[NN];
__device__ int   g_rowptr[NN + 1];
__device__ int   g_cursor[NN];
__device__ int   g_col[EE];
__device__ int   g_root[BG + 1];
__device__ int   g_bsum[SCAN_BLKS];
__device__ int   g_boff[SCAN_BLKS];
__device__ int   g_scnt;   // scan arrival counter (reset each launch)
__device__ int   g_sgo;    // scan top-done flag (reset each launch)
__device__ float g_h1[NN * D];
__device__ float g_h2[NN * D];
// W in per-thread mma-fragment layout: [layer][k_step 16][n_atom 16][lane 32]
// each uint4 = {bh0, bh1, bl0, bl1}
__device__ uint4 g_Wfrag[3 * 16 * 16 * 32];

// ---------------- fused init: zero deg, roots, scan flags, W fragment prep ----------------
__global__ void k_initprep(const int* __restrict__ batch,
                           const float* __restrict__ Wl1, const float* __restrict__ Wr1,
                           const float* __restrict__ Wl2, const float* __restrict__ Wr2,
                           const float* __restrict__ Wl3, const float* __restrict__ Wr3) {
    int i = blockIdx.x * blockDim.x + threadIdx.x;
    if (i < NN) {
        g_deg[i] = 0;
        int b = batch[i];
        if (i == 0 || batch[i - 1] != b) g_root[b] = i;
        if (i == 0) { g_root[BG] = NN; g_scnt = 0; g_sgo = 0; }
    }
    if (i < 3 * 16 * 16 * 32) {
        int L    = i >> 13;
        int rem  = i & 8191;
        int t    = rem >> 9;          // k_step 0..15
        int na   = (rem >> 5) & 15;   // n_atom 0..15
        int lane = rem & 31;
        const float* Wl = (L == 0) ? Wl1 : (L == 1) ? Wl2 : Wl3;
        const float* Wr = (L == 0) ? Wr1 : (L == 1) ? Wr2 : Wr3;
        int n  = na * 8 + (lane >> 2);
        int k0 = t * 16 + (lane & 3) * 2;
        float w[4];
#pragma unroll
        for (int q = 0; q < 4; q++) {
            int k = k0 + (q >> 1) * 8 + (q & 1);  // k0, k0+1, k0+8, k0+9
            w[q] = (k < 128) ? Wl[k * 128 + n] : Wr[(k - 128) * 128 + n];
        }
        unsigned short h[4], l[4];
#pragma unroll
        for (int q = 0; q < 4; q++) {
            __nv_bfloat16 hb = __float2bfloat16(w[q]);
            __nv_bfloat16 lb = __float2bfloat16(w[q] - __bfloat162float(hb));
            h[q] = __bfloat16_as_ushort(hb);
            l[q] = __bfloat16_as_ushort(lb);
        }
        uint4 v;
        v.x = (uint32_t)h[0] | ((uint32_t)h[1] << 16);
        v.y = (uint32_t)h[2] | ((uint32_t)h[3] << 16);
        v.z = (uint32_t)l[0] | ((uint32_t)l[1] << 16);
        v.w = (uint32_t)l[2] | ((uint32_t)l[3] << 16);
        g_Wfrag[i] = v;
    }
}

__global__ void k_hist(const int* __restrict__ dst) {
    int e = blockIdx.x * blockDim.x + threadIdx.x;
    if (e < EE) atomicAdd(&g_deg[dst[e]], 1);
}

// ---------------- single-kernel scan: local scans + resident global barrier ----------------
__global__ void k_scan_one() {
    __shared__ int sc[1024];
    __shared__ int s_last;
    __shared__ int s_boff;
    __shared__ int tops[64];
    int t = threadIdx.x;
    int bid = blockIdx.x;
    int i = bid * 1024 + t;
    int d = (i < NN) ? g_deg[i] : 0;
    sc[t] = d;
    __syncthreads();
#pragma unroll
    for (int off = 1; off < 1024; off <<= 1) {
        int add = (t >= off) ? sc[t - off] : 0;
        __syncthreads();
        sc[t] += add;
        __syncthreads();
    }
    int excl = sc[t] - d;
    if (t == 1023) g_bsum[bid] = sc[1023];
    __syncthreads();
    if (t == 0) {
        __threadfence();
        int a = atomicAdd(&g_scnt, 1);
        s_last = (a == SCAN_BLKS - 1) ? 1 : 0;
    }
    __syncthreads();
    if (s_last) {
        if (t < 64) tops[t] = (t < SCAN_BLKS) ? *(volatile int*)&g_bsum[t] : 0;
        __syncthreads();
#pragma unroll
        for (int off = 1; off < 64; off <<= 1) {
            int add = (t < 64 && t >= off) ? tops[t - off] : 0;
            __syncthreads();
            if (t < 64) tops[t] += add;
            __syncthreads();
        }
        if (t < SCAN_BLKS) g_boff[t] = tops[t] - *(volatile int*)&g_bsum[t];
        if (t == SCAN_BLKS - 1) g_rowptr[NN] = tops[t];
        __syncthreads();
        if (t == 0) {
            __threadfence();
            atomicExch(&g_sgo, 1);
        }
    }
    if (t == 0) {
        while (atomicAdd(&g_sgo, 0) == 0) { }
        s_boff = *(volatile int*)&g_boff[bid];
    }
    __syncthreads();
    if (i < NN) {
        int v = excl + s_boff;
        g_rowptr[i] = v;
        g_cursor[i] = v;
    }
}

__global__ void k_fill(const int* __restrict__ src, const int* __restrict__ dst) {
    int e = blockIdx.x * blockDim.x + threadIdx.x;
    if (e < EE) {
        int d = dst[e];
        int p = atomicAdd(&g_cursor[d], 1);
        g_col[p] = src[e];
    }
}

// ---------------- fused aggregate + tensor-core GEMM (per 128-row tile) ----------------
// Phase 1: 8 warps x 16 nodes: mean over neighbors (8-way unrolled L2 gather),
//          converted straight into bf16 hi/lo MMA A-image in smem (K 0..127).
// Phase 2: mma over mean image (chunks 0,1) + staged feat chunks (2,3).
// 3-term bf16 split: D = Ah*Bh + Ah*Bl + Al*Bh (fp32 accumulate).
#define MPITCH 68     // mean image pitch (u32 words); 68 mod 32 == 36 mod 32 -> same banks
#define FPITCH 36
#define SM_MLO (128 * MPITCH)
#define SM_AHI (2 * 128 * MPITCH)
#define SM_ALO (2 * 128 * MPITCH + 128 * FPITCH)
#define FUSED_SMEM ((2 * 128 * MPITCH + 2 * 128 * FPITCH) * 4)   // 106496 B

__device__ __forceinline__ void mma_bf16(float* c, const uint32_t* a,
                                         uint32_t b0, uint32_t b1) {
    asm("mma.sync.aligned.m16n8k16.row.col.f32.bf16.bf16.f32 "
        "{%0,%1,%2,%3}, {%4,%5,%6,%7}, {%8,%9}, {%0,%1,%2,%3};"
        : "+f"(c[0]), "+f"(c[1]), "+f"(c[2]), "+f"(c[3])
        : "r"(a[0]), "r"(a[1]), "r"(a[2]), "r"(a[3]), "r"(b0), "r"(b1));
}

__device__ __forceinline__ uint32_t pack_hi(float a, float b) {
    return (uint32_t)__bfloat16_as_ushort(__float2bfloat16(a)) |
           ((uint32_t)__bfloat16_as_ushort(__float2bfloat16(b)) << 16);
}
__device__ __forceinline__ uint32_t pack_lo(float a, float b) {
    __nv_bfloat16 ha = __float2bfloat16(a);
    __nv_bfloat16 hb = __float2bfloat16(b);
    return (uint32_t)__bfloat16_as_ushort(__float2bfloat16(a - __bfloat162float(ha))) |
           ((uint32_t)__bfloat16_as_ushort(__float2bfloat16(b - __bfloat162float(hb))) << 16);
}

__global__ __launch_bounds__(256, 2)
void k_agg_gemm(const float* __restrict__ feat, const uint4* __restrict__ Wfrag,
                const float* __restrict__ bias, float* __restrict__ out) {
    extern __shared__ uint32_t sm[];
    uint32_t* sMhi = sm;              // [128][MPITCH]  mean bf16x2 hi (K 0..127)
    uint32_t* sMlo = sm + SM_MLO;     // [128][MPITCH]  mean bf16x2 lo
    uint32_t* sAhi = sm + SM_AHI;     // [128][FPITCH]  feat chunk hi
    uint32_t* sAlo = sm + SM_ALO;     // [128][FPITCH]  feat chunk lo

    const int tid  = threadIdx.x;
    const int wid  = tid >> 5;
    const int lane = tid & 31;
    const int wr = wid >> 2;           // 0..1
    const int wc = wid & 3;            // 0..3
    const int row0 = blockIdx.x * 128;

    // ---- phase 1: gather means, write bf16 hi/lo image ----
    {
        const float4* f4 = (const float4*)feat;
        for (int j = 0; j < 16; j++) {
            int nl = wid * 16 + j;
            int grow = row0 + nl;
            float4 acc = make_float4(0.f, 0.f, 0.f, 0.f);
            if (grow < NN) {
                int s = g_rowptr[grow];
                int e = g_rowptr[grow + 1];
                int i = s;
                for (; i + 8 <= e; i += 8) {
                    int c[8];
#pragma unroll
                    for (int q = 0; q < 8; q++) c[q] = __ldg(&g_col[i + q]);
                    float4 v[8];
#pragma unroll
                    for (int q = 0; q < 8; q++) v[q] = __ldg(&f4[c[q] * 32 + lane]);
#pragma unroll
                    for (int q = 0; q < 8; q++) {
                        acc.x += v[q].x; acc.y += v[q].y;
                        acc.z += v[q].z; acc.w += v[q].w;
                    }
                }
                for (; i < e; i++) {
                    int c = __ldg(&g_col[i]);
                    float4 v = __ldg(&f4[c * 32 + lane]);
                    acc.x += v.x; acc.y += v.y; acc.z += v.z; acc.w += v.w;
                }
                int cnt = e - s;
                float inv = 1.0f / (float)(cnt > 0 ? cnt : 1);
                acc.x *= inv; acc.y *= inv; acc.z *= inv; acc.w *= inv;
            }
            uint2 hv, lv;
            hv.x = pack_hi(acc.x, acc.y);
            hv.y = pack_hi(acc.z, acc.w);
            lv.x = pack_lo(acc.x, acc.y);
            lv.y = pack_lo(acc.z, acc.w);
            *(uint2*)&sMhi[nl * MPITCH + lane * 2] = hv;
            *(uint2*)&sMlo[nl * MPITCH + lane * 2] = lv;
        }
    }
    __syncthreads();

    float acc[4][4][4];
#pragma unroll
    for (int i = 0; i < 4; i++)
#pragma unroll
        for (int j = 0; j < 4; j++)
#pragma unroll
            for (int r = 0; r < 4; r++) acc[i][j][r] = 0.f;

    const int rb = wr * 64 + (lane >> 2);

    // ---- chunks 0,1: mean image (no staging needed) ----
#pragma unroll
    for (int chunk = 0; chunk < 2; chunk++) {
#pragma unroll
        for (int t = 0; t < 4; t++) {
            uint4 B[4];
#pragma unroll
            for (int j = 0; j < 4; j++)
                B[j] = __ldg(&Wfrag[(((chunk * 4 + t) * 16) + (wc * 4 + j)) * 32 + lane]);
            const int cw = chunk * 32 + t * 8 + (lane & 3);
#pragma unroll
            for (int i = 0; i < 4; i++) {
                int base = (rb + i * 16) * MPITCH;
                uint32_t ah[4], al[4];
                ah[0] = sMhi[base + cw];
                ah[1] = sMhi[base + 8 * MPITCH + cw];
                ah[2] = sMhi[base + cw + 4];
                ah[3] = sMhi[base + 8 * MPITCH + cw + 4];
                al[0] = sMlo[base + cw];
                al[1] = sMlo[base + 8 * MPITCH + cw];
                al[2] = sMlo[base + cw + 4];
                al[3] = sMlo[base + 8 * MPITCH + cw + 4];
#pragma unroll
                for (int j = 0; j < 4; j++) {
                    mma_bf16(acc[i][j], ah, B[j].x, B[j].y);
                    mma_bf16(acc[i][j], ah, B[j].z, B[j].w);
                    mma_bf16(acc[i][j], al, B[j].x, B[j].y);
                }
            }
        }
    }

    // ---- chunks 2,3: self features, staged per 64-k ----
#pragma unroll
    for (int half64 = 0; half64 < 2; half64++) {
        const int kb = half64 * 64;
        {
            int r = tid >> 1;
            int half = tid & 1;
            int grow = row0 + r;
            const float4* Ag = (const float4*)(feat + (size_t)grow * D + kb);
#pragma unroll
            for (int q = 0; q < 8; q++) {
                float4 v = make_float4(0.f, 0.f, 0.f, 0.f);
                if (grow < NN) v = __ldg(&Ag[half * 8 + q]);
                uint2 hv, lv;
                hv.x = pack_hi(v.x, v.y);
                hv.y = pack_hi(v.z, v.w);
                lv.x = pack_lo(v.x, v.y);
                lv.y = pack_lo(v.z, v.w);
                int c = half * 16 + q * 2;
                *(uint2*)&sAhi[r * FPITCH + c] = hv;
                *(uint2*)&sAlo[r * FPITCH + c] = lv;
            }
        }
        __syncthreads();
        const int chunk = 2 + half64;
#pragma unroll
        for (int t = 0; t < 4; t++) {
            uint4 B[4];
#pragma unroll
            for (int j = 0; j < 4; j++)
                B[j] = __ldg(&Wfrag[(((chunk * 4 + t) * 16) + (wc * 4 + j)) * 32 + lane]);
            const int cw = t * 8 + (lane & 3);
#pragma unroll
            for (int i = 0; i < 4; i++) {
                int base = (rb + i * 16) * FPITCH;
                uint32_t ah[4], al[4];
                ah[0] = sAhi[base + cw];
                ah[1] = sAhi[base + 8 * FPITCH + cw];
                ah[2] = sAhi[base + cw + 4];
                ah[3] = sAhi[base + 8 * FPITCH + cw + 4];
                al[0] = sAlo[base + cw];
                al[1] = sAlo[base + 8 * FPITCH + cw];
                al[2] = sAlo[base + cw + 4];
                al[3] = sAlo[base + 8 * FPITCH + cw + 4];
#pragma unroll
                for (int j = 0; j < 4; j++) {
                    mma_bf16(acc[i][j], ah, B[j].x, B[j].y);
                    mma_bf16(acc[i][j], ah, B[j].z, B[j].w);
                    mma_bf16(acc[i][j], al, B[j].x, B[j].y);
                }
            }
        }
        __syncthreads();
    }

    // ---- epilogue: bias + relu, float2 stores ----
#pragma unroll
    for (int j = 0; j < 4; j++) {
        int col = wc * 32 + j * 8 + (lane & 3) * 2;
        float b0 = __ldg(&bias[col]);
        float b1 = __ldg(&bias[col + 1]);
#pragma unroll
        for (int i = 0; i < 4; i++) {
            int row = row0 + wr * 64 + i * 16 + (lane >> 2);
            if (row < NN) {
                float2 v0;
                v0.x = fmaxf(acc[i][j][0] + b0, 0.f);
                v0.y = fmaxf(acc[i][j][1] + b1, 0.f);
                *(float2*)(out + (size_t)row * D + col) = v0;
            }
            if (row + 8 < NN) {
                float2 v1;
                v1.x = fmaxf(acc[i][j][2] + b0, 0.f);
                v1.y = fmaxf(acc[i][j][3] + b1, 0.f);
                *(float2*)(out + (size_t)(row + 8) * D + col) = v1;
            }
        }
    }
}

// ---------------- fully fused tail: max-pool -> mlp1 -> mlp2 -> head ----------------
__global__ void k_tail(const float* __restrict__ h, const float* __restrict__ x,
                       const float* __restrict__ W1, const float* __restrict__ b1,
                       const float* __restrict__ W2, const float* __restrict__ b2,
                       const float* __restrict__ Wsm, const float* __restrict__ bsm,
                       const float* __restrict__ Wnews, const float* __restrict__ bnews,
                       const float* __restrict__ Wcat, const float* __restrict__ bcat,
                       float* __restrict__ out) {
    __shared__ float pool[128];
    __shared__ float pmax[256];
    __shared__ float f1s[256];
    __shared__ float f2s[128];
    __shared__ float xroot[128];
    int g = blockIdx.x;
    int tid = threadIdx.x;  // 0..255
    int col = tid & 127, half = tid >> 7;
    int s = g_root[g], e = g_root[g + 1];
    float m = -3.4e38f;
    for (int n = s + half; n < e; n += 2) m = fmaxf(m, h[(size_t)n * D + col]);
    pmax[tid] = m;
    __syncthreads();
    if (tid < 128) {
        pool[tid] = fmaxf(pmax[tid], pmax[tid + 128]);
        xroot[tid] = x[(size_t)s * D + tid];
    }
    __syncthreads();
    float a1 = b1[tid];
#pragma unroll 16
    for (int k = 0; k < 128; k++) a1 += pool[k] * W1[k * 256 + tid];
    f1s[tid] = fmaxf(a1, 0.f);
    __syncthreads();
    if (tid < 128) {
        float a2 = b2[tid];
#pragma unroll 16
        for (int k = 0; k < 256; k++) a2 += f1s[k] * W2[k * 128 + tid];
        f2s[tid] = fmaxf(a2, 0.f);
    }
    __syncthreads();
    if (tid < 32) {
        int kb = tid * 4;
        float s0 = 0.f, s1 = 0.f, n0 = 0.f, n1 = 0.f;
#pragma unroll
        for (int t = 0; t < 4; t++) {
            float fv = f2s[kb + t];
            float xv = xroot[kb + t];
            s0 += fv * Wsm[(kb + t) * 2 + 0];
            s1 += fv * Wsm[(kb + t) * 2 + 1];
            n0 += xv * Wnews[(kb + t) * 2 + 0];
            n1 += xv * Wnews[(kb + t) * 2 + 1];
        }
#pragma unroll
        for (int off = 16; off > 0; off >>= 1) {
            s0 += __shfl_down_sync(0xffffffffu, s0, off);
            s1 += __shfl_down_sync(0xffffffffu, s1, off);
            n0 += __shfl_down_sync(0xffffffffu, n0, off);
            n1 += __shfl_down_sync(0xffffffffu, n1, off);
        }
        if (tid == 0) {
            float h0 = fmaxf(s0 + bsm[0], 0.f);
            float h1 = fmaxf(s1 + bsm[1], 0.f);
            float m0 = fmaxf(n0 + bnews[0], 0.f);
            float m1 = fmaxf(n1 + bnews[1], 0.f);
            float z = h0 * Wcat[0] + h1 * Wcat[1] + m0 * Wcat[2] + m1 * Wcat[3] + bcat[0];
            out[g] = 1.0f / (1.0f + expf(-z));
        }
    }
}

// ---------------- launch ----------------
extern "C" void kernel_launch(void* const* d_in, const int* in_sizes, int n_in,
                              void* d_out, int out_size) {
    const float* x     = (const float*)d_in[0];
    const int*   ei    = (const int*)d_in[1];
    const int*   src   = ei;
    const int*   dst   = ei + EE;
    const int*   batch = (const int*)d_in[2];
    const float* Wl1 = (const float*)d_in[3];
    const float* Wr1 = (const float*)d_in[4];
    const float* bl1 = (const float*)d_in[5];
    const float* Wl2 = (const float*)d_in[6];
    const float* Wr2 = (const float*)d_in[7];
    const float* bl2 = (const float*)d_in[8];
    const float* Wl3 = (const float*)d_in[9];
    const float* Wr3 = (const float*)d_in[10];
    const float* bl3 = (const float*)d_in[11];
    const float* W_f1 = (const float*)d_in[12];
    const float* b_f1 = (const float*)d_in[13];
    const float* W_f2 = (const float*)d_in[14];
    const float* b_f2 = (const float*)d_in[15];
    const float* W_sm = (const float*)d_in[16];
    const float* b_sm = (const float*)d_in[17];
    const float* W_news = (const float*)d_in[18];
    const float* b_news = (const float*)d_in[19];
    const float* W_cat = (const float*)d_in[20];
    const float* b_cat = (const float*)d_in[21];
    float* out = (float*)d_out;

    float *h1, *h2;
    uint4* wfrag;
    cudaGetSymbolAddress((void**)&h1, g_h1);
    cudaGetSymbolAddress((void**)&h2, g_h2);
    cudaGetSymbolAddress((void**)&wfrag, g_Wfrag);

    const int TB = 256;
    const int gN = (NN + TB - 1) / TB;
    const int gE = (EE + TB - 1) / TB;

    // CSR build + roots + weight fragment prep
    k_initprep<<<gN, TB>>>(batch, Wl1, Wr1, Wl2, Wr2, Wl3, Wr3);
    k_hist<<<gE, TB>>>(dst);
    k_scan_one<<<SCAN_BLKS, 1024>>>();
    k_fill<<<gE, TB>>>(src, dst);

    const int gGemm = (NN + 127) / 128;        // 391
    cudaFuncSetAttribute(k_agg_gemm, cudaFuncAttributeMaxDynamicSharedMemorySize,
                         FUSED_SMEM);

    // fused aggregate+gemm per layer
    k_agg_gemm<<<gGemm, TB, FUSED_SMEM>>>(x,  wfrag,         bl1, h1);
    k_agg_gemm<<<gGemm, TB, FUSED_SMEM>>>(h1, wfrag + 8192,  bl2, h2);
    k_agg_gemm<<<gGemm, TB, FUSED_SMEM>>>(h2, wfrag + 16384, bl3, h1);

    // fused tail
    k_tail<<<BG, TB>>>(h1, x, W_f1, b_f1, W_f2, b_f2, W_sm, b_sm,
                       W_news, b_news, W_cat, b_cat, out);
}

// round 13
// speedup vs baseline: 1.1121x; 1.1121x over previous
#include <cuda_runtime.h>
#include <cuda_bf16.h>
#include <math.h>
#include <stdint.h>

#define NN 50000
#define EE 800000
#define BG 512
#define D  128
#define SCAN_BLKS 49   // ceil(50000 / 1024)

// ---------------- scratch (static device globals; no allocation) ----------------
__device__ int   g_deg[NN];
__device__ int   g_rowptr[NN + 1];
__device__ int   g_cursor[NN];
__device__ int   g_col[EE];
__device__ int   g_root[BG + 1];
__device__ int   g_bsum[SCAN_BLKS];
__device__ int   g_boff[SCAN_BLKS];
__device__ int   g_scnt;   // scan arrival counter (reset each launch)
__device__ int   g_sgo;    // scan top-done flag (reset each launch)
__device__ float g_mean[NN * D];
__device__ float g_h1[NN * D];
__device__ float g_h2[NN * D];
// W in per-thread mma-fragment layout: [layer][k_step 16][n_atom 16][lane 32]
// each uint4 = {bh0, bh1, bl0, bl1}
__device__ uint4 g_Wfrag[3 * 16 * 16 * 32];

// ---------------- fused init: zero deg, roots, scan flags, W fragment prep ----------------
__global__ void k_initprep(const int* __restrict__ batch,
                           const float* __restrict__ Wl1, const float* __restrict__ Wr1,
                           const float* __restrict__ Wl2, const float* __restrict__ Wr2,
                           const float* __restrict__ Wl3, const float* __restrict__ Wr3) {
    int i = blockIdx.x * blockDim.x + threadIdx.x;
    if (i < NN) {
        g_deg[i] = 0;
        int b = batch[i];
        if (i == 0 || batch[i - 1] != b) g_root[b] = i;
        if (i == 0) { g_root[BG] = NN; g_scnt = 0; g_sgo = 0; }
    }
    if (i < 3 * 16 * 16 * 32) {
        int L    = i >> 13;
        int rem  = i & 8191;
        int t    = rem >> 9;          // k_step 0..15
        int na   = (rem >> 5) & 15;   // n_atom 0..15
        int lane = rem & 31;
        const float* Wl = (L == 0) ? Wl1 : (L == 1) ? Wl2 : Wl3;
        const float* Wr = (L == 0) ? Wr1 : (L == 1) ? Wr2 : Wr3;
        int n  = na * 8 + (lane >> 2);
        int k0 = t * 16 + (lane & 3) * 2;
        float w[4];
#pragma unroll
        for (int q = 0; q < 4; q++) {
            int k = k0 + (q >> 1) * 8 + (q & 1);  // k0, k0+1, k0+8, k0+9
            w[q] = (k < 128) ? Wl[k * 128 + n] : Wr[(k - 128) * 128 + n];
        }
        unsigned short h[4], l[4];
#pragma unroll
        for (int q = 0; q < 4; q++) {
            __nv_bfloat16 hb = __float2bfloat16(w[q]);
            __nv_bfloat16 lb = __float2bfloat16(w[q] - __bfloat162float(hb));
            h[q] = __bfloat16_as_ushort(hb);
            l[q] = __bfloat16_as_ushort(lb);
        }
        uint4 v;
        v.x = (uint32_t)h[0] | ((uint32_t)h[1] << 16);
        v.y = (uint32_t)h[2] | ((uint32_t)h[3] << 16);
        v.z = (uint32_t)l[0] | ((uint32_t)l[1] << 16);
        v.w = (uint32_t)l[2] | ((uint32_t)l[3] << 16);
        g_Wfrag[i] = v;
    }
}

// ---------------- histogram: 4 edges per thread (MLP=4 on the atomic chain) ----------------
__global__ void k_hist(const int4* __restrict__ dst4) {
    int e = blockIdx.x * blockDim.x + threadIdx.x;
    if (e < EE / 4) {
        int4 d = __ldg(&dst4[e]);
        atomicAdd(&g_deg[d.x], 1);
        atomicAdd(&g_deg[d.y], 1);
        atomicAdd(&g_deg[d.z], 1);
        atomicAdd(&g_deg[d.w], 1);
    }
}

// ---------------- single-kernel scan: local scans + resident global barrier ----------------
__global__ void k_scan_one() {
    __shared__ int sc[1024];
    __shared__ int s_last;
    __shared__ int s_boff;
    __shared__ int tops[64];
    int t = threadIdx.x;
    int bid = blockIdx.x;
    int i = bid * 1024 + t;
    int d = (i < NN) ? g_deg[i] : 0;
    sc[t] = d;
    __syncthreads();
#pragma unroll
    for (int off = 1; off < 1024; off <<= 1) {
        int add = (t >= off) ? sc[t - off] : 0;
        __syncthreads();
        sc[t] += add;
        __syncthreads();
    }
    int excl = sc[t] - d;
    if (t == 1023) g_bsum[bid] = sc[1023];
    __syncthreads();
    if (t == 0) {
        __threadfence();
        int a = atomicAdd(&g_scnt, 1);
        s_last = (a == SCAN_BLKS - 1) ? 1 : 0;
    }
    __syncthreads();
    if (s_last) {
        if (t < 64) tops[t] = (t < SCAN_BLKS) ? *(volatile int*)&g_bsum[t] : 0;
        __syncthreads();
#pragma unroll
        for (int off = 1; off < 64; off <<= 1) {
            int add = (t < 64 && t >= off) ? tops[t - off] : 0;
            __syncthreads();
            if (t < 64) tops[t] += add;
            __syncthreads();
        }
        if (t < SCAN_BLKS) g_boff[t] = tops[t] - *(volatile int*)&g_bsum[t];
        if (t == SCAN_BLKS - 1) g_rowptr[NN] = tops[t];
        __syncthreads();
        if (t == 0) {
            __threadfence();
            atomicExch(&g_sgo, 1);
        }
    }
    if (t == 0) {
        while (atomicAdd(&g_sgo, 0) == 0) { }
        s_boff = *(volatile int*)&g_boff[bid];
    }
    __syncthreads();
    if (i < NN) {
        int v = excl + s_boff;
        g_rowptr[i] = v;
        g_cursor[i] = v;
    }
}

// ---------------- bucket fill: 4 edges per thread ----------------
__global__ void k_fill(const int4* __restrict__ src4, const int4* __restrict__ dst4) {
    int e = blockIdx.x * blockDim.x + threadIdx.x;
    if (e < EE / 4) {
        int4 s = __ldg(&src4[e]);
        int4 d = __ldg(&dst4[e]);
        int p0 = atomicAdd(&g_cursor[d.x], 1);
        int p1 = atomicAdd(&g_cursor[d.y], 1);
        int p2 = atomicAdd(&g_cursor[d.z], 1);
        int p3 = atomicAdd(&g_cursor[d.w], 1);
        g_col[p0] = s.x;
        g_col[p1] = s.y;
        g_col[p2] = s.z;
        g_col[p3] = s.w;
    }
}

// ---------------- mean aggregation: warp per node, lane = one float4, 8-way unroll ----------------
__global__ void k_aggregate(const float* __restrict__ feat, float* __restrict__ mean) {
    int warp = (blockIdx.x * blockDim.x + threadIdx.x) >> 5;
    int lane = threadIdx.x & 31;
    if (warp >= NN) return;
    int s = g_rowptr[warp];
    int e = g_rowptr[warp + 1];
    float4 acc = make_float4(0.f, 0.f, 0.f, 0.f);
    const float4* f4 = (const float4*)feat;
    int i = s;
    for (; i + 8 <= e; i += 8) {
        int c[8];
#pragma unroll
        for (int q = 0; q < 8; q++) c[q] = __ldg(&g_col[i + q]);
        float4 v[8];
#pragma unroll
        for (int q = 0; q < 8; q++) v[q] = __ldg(&f4[c[q] * 32 + lane]);
#pragma unroll
        for (int q = 0; q < 8; q++) {
            acc.x += v[q].x; acc.y += v[q].y; acc.z += v[q].z; acc.w += v[q].w;
        }
    }
    for (; i < e; i++) {
        int c = __ldg(&g_col[i]);
        float4 v = __ldg(&f4[c * 32 + lane]);
        acc.x += v.x; acc.y += v.y; acc.z += v.z; acc.w += v.w;
    }
    int cnt = e - s;
    float inv = 1.0f / (float)(cnt > 0 ? cnt : 1);
    acc.x *= inv; acc.y *= inv; acc.z *= inv; acc.w *= inv;
    ((float4*)mean)[warp * 32 + lane] = acc;
}

// ---------------- tensor-core SAGE GEMM ----------------
// out[128 rows tile][128] = relu([mean|feat] @ W + bias), K = 256.
// 3-term bf16 split: D = Ah*Bh + Ah*Bl + Al*Bh (fp32 accumulate).
// 8 warps: warp_row (2) x warp_col (4); warp tile 64x32.
#define APITCH 36

__device__ __forceinline__ void mma_bf16(float* c, const uint32_t* a,
                                         uint32_t b0, uint32_t b1) {
    asm("mma.sync.aligned.m16n8k16.row.col.f32.bf16.bf16.f32 "
        "{%0,%1,%2,%3}, {%4,%5,%6,%7}, {%8,%9}, {%0,%1,%2,%3};"
        : "+f"(c[0]), "+f"(c[1]), "+f"(c[2]), "+f"(c[3])
        : "r"(a[0]), "r"(a[1]), "r"(a[2]), "r"(a[3]), "r"(b0), "r"(b1));
}

__global__ __launch_bounds__(256)
void k_gemm_mma(const float* __restrict__ Amean, const float* __restrict__ Afeat,
                const uint4* __restrict__ Wfrag, const float* __restrict__ bias,
                float* __restrict__ out) {
    __shared__ uint32_t sAhi[128 * APITCH];
    __shared__ uint32_t sAlo[128 * APITCH];

    const int tid  = threadIdx.x;
    const int wid  = tid >> 5;
    const int lane = tid & 31;
    const int wr = wid >> 2;           // 0..1
    const int wc = wid & 3;            // 0..3
    const int row0 = blockIdx.x * 128;

    float acc[4][4][4];
#pragma unroll
    for (int i = 0; i < 4; i++)
#pragma unroll
        for (int j = 0; j < 4; j++)
#pragma unroll
            for (int r = 0; r < 4; r++) acc[i][j][r] = 0.f;

    for (int chunk = 0; chunk < 4; chunk++) {
        const float* A = (chunk < 2) ? Amean : Afeat;
        const int kb = (chunk & 1) * 64;

        // ---- stage A chunk: 128 rows x 64 k -> bf16 hi/lo smem images ----
        {
            int r = tid >> 1;
            int half = tid & 1;
            int grow = row0 + r;
            const float4* Ag = (const float4*)(A + (size_t)grow * D + kb);
#pragma unroll
            for (int q = 0; q < 8; q++) {
                float4 v = make_float4(0.f, 0.f, 0.f, 0.f);
                if (grow < NN) v = __ldg(&Ag[half * 8 + q]);
                __nv_bfloat16 hx = __float2bfloat16(v.x);
                __nv_bfloat16 hy = __float2bfloat16(v.y);
                __nv_bfloat16 hz = __float2bfloat16(v.z);
                __nv_bfloat16 hw = __float2bfloat16(v.w);
                uint2 hv, lv;
                hv.x = (uint32_t)__bfloat16_as_ushort(hx) |
                       ((uint32_t)__bfloat16_as_ushort(hy) << 16);
                hv.y = (uint32_t)__bfloat16_as_ushort(hz) |
                       ((uint32_t)__bfloat16_as_ushort(hw) << 16);
                __nv_bfloat16 lx = __float2bfloat16(v.x - __bfloat162float(hx));
                __nv_bfloat16 ly = __float2bfloat16(v.y - __bfloat162float(hy));
                __nv_bfloat16 lz = __float2bfloat16(v.z - __bfloat162float(hz));
                __nv_bfloat16 lw = __float2bfloat16(v.w - __bfloat162float(hw));
                lv.x = (uint32_t)__bfloat16_as_ushort(lx) |
                       ((uint32_t)__bfloat16_as_ushort(ly) << 16);
                lv.y = (uint32_t)__bfloat16_as_ushort(lz) |
                       ((uint32_t)__bfloat16_as_ushort(lw) << 16);
                int c = half * 16 + q * 2;
                *(uint2*)&sAhi[r * APITCH + c] = hv;
                *(uint2*)&sAlo[r * APITCH + c] = lv;
            }
        }
        __syncthreads();

        // ---- mma over 4 k-steps of 16 ----
#pragma unroll
        for (int t = 0; t < 4; t++) {
            uint4 B[4];
#pragma unroll
            for (int j = 0; j < 4; j++)
                B[j] = __ldg(&Wfrag[(((chunk * 4 + t) * 16) + (wc * 4 + j)) * 32 + lane]);

            const int rb = wr * 64 + (lane >> 2);
            const int cw = t * 8 + (lane & 3);
#pragma unroll
            for (int i = 0; i < 4; i++) {
                int base = (rb + i * 16) * APITCH;
                uint32_t ah[4], al[4];
                ah[0] = sAhi[base + cw];
                ah[1] = sAhi[base + 8 * APITCH + cw];
                ah[2] = sAhi[base + cw + 4];
                ah[3] = sAhi[base + 8 * APITCH + cw + 4];
                al[0] = sAlo[base + cw];
                al[1] = sAlo[base + 8 * APITCH + cw];
                al[2] = sAlo[base + cw + 4];
                al[3] = sAlo[base + 8 * APITCH + cw + 4];
#pragma unroll
                for (int j = 0; j < 4; j++) {
                    mma_bf16(acc[i][j], ah, B[j].x, B[j].y);  // Ah*Bh
                    mma_bf16(acc[i][j], ah, B[j].z, B[j].w);  // Ah*Bl
                    mma_bf16(acc[i][j], al, B[j].x, B[j].y);  // Al*Bh
                }
            }
        }
        __syncthreads();
    }

    // ---- epilogue: bias + relu, float2 stores ----
#pragma unroll
    for (int j = 0; j < 4; j++) {
        int col = wc * 32 + j * 8 + (lane & 3) * 2;
        float b0 = __ldg(&bias[col]);
        float b1 = __ldg(&bias[col + 1]);
#pragma unroll
        for (int i = 0; i < 4; i++) {
            int row = row0 + wr * 64 + i * 16 + (lane >> 2);
            if (row < NN) {
                float2 v0;
                v0.x = fmaxf(acc[i][j][0] + b0, 0.f);
                v0.y = fmaxf(acc[i][j][1] + b1, 0.f);
                *(float2*)(out + (size_t)row * D + col) = v0;
            }
            if (row + 8 < NN) {
                float2 v1;
                v1.x = fmaxf(acc[i][j][2] + b0, 0.f);
                v1.y = fmaxf(acc[i][j][3] + b1, 0.f);
                *(float2*)(out + (size_t)(row + 8) * D + col) = v1;
            }
        }
    }
}

// ---------------- fully fused tail: max-pool -> mlp1 -> mlp2 -> head ----------------
__global__ void k_tail(const float* __restrict__ h, const float* __restrict__ x,
                       const float* __restrict__ W1, const float* __restrict__ b1,
                       const float* __restrict__ W2, const float* __restrict__ b2,
                       const float* __restrict__ Wsm, const float* __restrict__ bsm,
                       const float* __restrict__ Wnews, const float* __restrict__ bnews,
                       const float* __restrict__ Wcat, const float* __restrict__ bcat,
                       float* __restrict__ out) {
    __shared__ float pool[128];
    __shared__ float pmax[256];
    __shared__ float f1s[256];
    __shared__ float f2s[128];
    __shared__ float xroot[128];
    int g = blockIdx.x;
    int tid = threadIdx.x;  // 0..255
    int col = tid & 127, half = tid >> 7;
    int s = g_root[g], e = g_root[g + 1];
    float m = -3.4e38f;
    for (int n = s + half; n < e; n += 2) m = fmaxf(m, h[(size_t)n * D + col]);
    pmax[tid] = m;
    __syncthreads();
    if (tid < 128) {
        pool[tid] = fmaxf(pmax[tid], pmax[tid + 128]);
        xroot[tid] = x[(size_t)s * D + tid];
    }
    __syncthreads();
    float a1 = b1[tid];
#pragma unroll 16
    for (int k = 0; k < 128; k++) a1 += pool[k] * W1[k * 256 + tid];
    f1s[tid] = fmaxf(a1, 0.f);
    __syncthreads();
    if (tid < 128) {
        float a2 = b2[tid];
#pragma unroll 16
        for (int k = 0; k < 256; k++) a2 += f1s[k] * W2[k * 128 + tid];
        f2s[tid] = fmaxf(a2, 0.f);
    }
    __syncthreads();
    if (tid < 32) {
        int kb = tid * 4;
        float s0 = 0.f, s1 = 0.f, n0 = 0.f, n1 = 0.f;
#pragma unroll
        for (int t = 0; t < 4; t++) {
            float fv = f2s[kb + t];
            float xv = xroot[kb + t];
            s0 += fv * Wsm[(kb + t) * 2 + 0];
            s1 += fv * Wsm[(kb + t) * 2 + 1];
            n0 += xv * Wnews[(kb + t) * 2 + 0];
            n1 += xv * Wnews[(kb + t) * 2 + 1];
        }
#pragma unroll
        for (int off = 16; off > 0; off >>= 1) {
            s0 += __shfl_down_sync(0xffffffffu, s0, off);
            s1 += __shfl_down_sync(0xffffffffu, s1, off);
            n0 += __shfl_down_sync(0xffffffffu, n0, off);
            n1 += __shfl_down_sync(0xffffffffu, n1, off);
        }
        if (tid == 0) {
            float h0 = fmaxf(s0 + bsm[0], 0.f);
            float h1 = fmaxf(s1 + bsm[1], 0.f);
            float m0 = fmaxf(n0 + bnews[0], 0.f);
            float m1 = fmaxf(n1 + bnews[1], 0.f);
            float z = h0 * Wcat[0] + h1 * Wcat[1] + m0 * Wcat[2] + m1 * Wcat[3] + bcat[0];
            out[g] = 1.0f / (1.0f + expf(-z));
        }
    }
}

// ---------------- launch ----------------
extern "C" void kernel_launch(void* const* d_in, const int* in_sizes, int n_in,
                              void* d_out, int out_size) {
    const float* x     = (const float*)d_in[0];
    const int*   ei    = (const int*)d_in[1];
    const int4*  src4  = (const int4*)ei;
    const int4*  dst4  = (const int4*)(ei + EE);
    const int*   batch = (const int*)d_in[2];
    const float* Wl1 = (const float*)d_in[3];
    const float* Wr1 = (const float*)d_in[4];
    const float* bl1 = (const float*)d_in[5];
    const float* Wl2 = (const float*)d_in[6];
    const float* Wr2 = (const float*)d_in[7];
    const float* bl2 = (const float*)d_in[8];
    const float* Wl3 = (const float*)d_in[9];
    const float* Wr3 = (const float*)d_in[10];
    const float* bl3 = (const float*)d_in[11];
    const float* W_f1 = (const float*)d_in[12];
    const float* b_f1 = (const float*)d_in[13];
    const float* W_f2 = (const float*)d_in[14];
    const float* b_f2 = (const float*)d_in[15];
    const float* W_sm = (const float*)d_in[16];
    const float* b_sm = (const float*)d_in[17];
    const float* W_news = (const float*)d_in[18];
    const float* b_news = (const float*)d_in[19];
    const float* W_cat = (const float*)d_in[20];
    const float* b_cat = (const float*)d_in[21];
    float* out = (float*)d_out;

    float *mean, *h1, *h2;
    uint4* wfrag;
    cudaGetSymbolAddress((void**)&mean, g_mean);
    cudaGetSymbolAddress((void**)&h1, g_h1);
    cudaGetSymbolAddress((void**)&h2, g_h2);
    cudaGetSymbolAddress((void**)&wfrag, g_Wfrag);

    const int TB = 256;
    const int gN = (NN + TB - 1) / TB;
    const int gE4 = (EE / 4 + TB - 1) / TB;

    // CSR build + roots + weight fragment prep
    k_initprep<<<gN, TB>>>(batch, Wl1, Wr1, Wl2, Wr2, Wl3, Wr3);
    k_hist<<<gE4, TB>>>(dst4);
    k_scan_one<<<SCAN_BLKS, 1024>>>();
    k_fill<<<gE4, TB>>>(src4, dst4);

    const int gAgg = (NN * 32 + TB - 1) / TB;  // warp per node
    const int gGemm = (NN + 127) / 128;        // 391

    // layer 1: x -> h1
    k_aggregate<<<gAgg, TB>>>(x, mean);
    k_gemm_mma<<<gGemm, TB>>>(mean, x, wfrag, bl1, h1);
    // layer 2: h1 -> h2
    k_aggregate<<<gAgg, TB>>>(h1, mean);
    k_gemm_mma<<<gGemm, TB>>>(mean, h1, wfrag + 8192, bl2, h2);
    // layer 3: h2 -> h1
    k_aggregate<<<gAgg, TB>>>(h2, mean);
    k_gemm_mma<<<gGemm, TB>>>(mean, h2, wfrag + 16384, bl3, h1);

    // fused tail
    k_tail<<<BG, TB>>>(h1, x, W_f1, b_f1, W_f2, b_f2, W_sm, b_sm,
                       W_news, b_news, W_cat, b_cat, out);
}